// round 17
// baseline (speedup 1.0000x reference)
#include <cuda_runtime.h>
#include <cuda_fp16.h>
#include <math.h>
#include <stdint.h>

#define N_NODES 10000
#define N_EDGES 640000
#define HD      128
#define NHEADS  8
#define TILE    128                 // k_proj tile
#define TILE_M  64                  // k_edge tile (per half)
#define NTILES64 (N_EDGES / TILE_M) // 10000
#define EDGE_GRID 148
#define SA_STRIDE 132               // k_proj tf32 tiles
#define SE_STRIDE 136               // e bufs fp32
#define SWH_STRIDE 144              // fp16 W, k-interleaved
#define SACC_STRIDE 136             // fp16 acc rows

// scratch (allocation-free rule: __device__ globals)
__device__ float g_Q[N_NODES * HD];
__device__ float g_K[N_NODES * HD];
__device__ float g_V[N_NODES * HD];
__device__ float g_Z[N_NODES * NHEADS];

// smem layout (bytes)
#define SO_WH    0                                        // 128*144 half = 36864
#define SO_BE    (SO_WH + 128 * SWH_STRIDE * 2)           // 512
#define SO_HALF0 (SO_BE + 512)
#define HALF_EBUF  (2 * TILE_M * SE_STRIDE * 4)           // 69632
#define HALF_ACC   (TILE_M * SACC_STRIDE * 2)             // 17408
#define HALF_BYTES (HALF_EBUF + HALF_ACC)                 // 87040
#define SMEM_EDGE (SO_HALF0 + 2 * HALF_BYTES)             // ~206.5 KB
#define SMEM_PROJ ((2 * TILE * SA_STRIDE + 128) * 4)

extern __shared__ char smem_raw[];

__device__ __forceinline__ float cvt_tf32(float x) {
    unsigned u;
    asm("cvt.rna.tf32.f32 %0, %1;" : "=r"(u) : "f"(x));
    return __uint_as_float(u);
}

// pack two fp32 into half2 (lo = f.x)
__device__ __forceinline__ unsigned cvt_h2(float2 f) {
    unsigned r;
    asm("cvt.rn.f16x2.f32 %0, %1, %2;" : "=r"(r) : "f"(f.y), "f"(f.x));
    return r;
}

__device__ __forceinline__ void mma_tf32(float c[4],
                                         unsigned a0, unsigned a1, unsigned a2, unsigned a3,
                                         unsigned b0, unsigned b1) {
    asm volatile(
        "mma.sync.aligned.m16n8k8.row.col.f32.tf32.tf32.f32 "
        "{%0,%1,%2,%3}, {%4,%5,%6,%7}, {%8,%9}, {%0,%1,%2,%3};"
        : "+f"(c[0]), "+f"(c[1]), "+f"(c[2]), "+f"(c[3])
        : "r"(a0), "r"(a1), "r"(a2), "r"(a3), "r"(b0), "r"(b1));
}

__device__ __forceinline__ void mma_f16(float c[4], const unsigned a[4],
                                        unsigned b0, unsigned b1) {
    asm volatile(
        "mma.sync.aligned.m16n8k16.row.col.f32.f16.f16.f32 "
        "{%0,%1,%2,%3}, {%4,%5,%6,%7}, {%8,%9}, {%0,%1,%2,%3};"
        : "+f"(c[0]), "+f"(c[1]), "+f"(c[2]), "+f"(c[3])
        : "r"(a[0]), "r"(a[1]), "r"(a[2]), "r"(a[3]), "r"(b0), "r"(b1));
}

template <int NT>
__device__ __forceinline__ void load_tile_tf32(float* dst, const float* __restrict__ src,
                                               int rows, int tid) {
    for (int idx = tid; idx < TILE * 32; idx += NT) {
        int row = idx >> 5, q = idx & 31;
        float4 v = make_float4(0.f, 0.f, 0.f, 0.f);
        if (row < rows) v = ((const float4*)(src + (size_t)row * 128))[q];
        float4 o = make_float4(cvt_tf32(v.x), cvt_tf32(v.y), cvt_tf32(v.z), cvt_tf32(v.w));
        *((float4*)(dst + row * SA_STRIDE + q * 4)) = o;
    }
}

// cp.async a FULL 64x128 fp32 tile into [64][SE_STRIDE], 128 producer threads.
// 64 rows x 32 16B-chunks = 2048 chunks -> 16 iterations of 128 threads.
// (Round 13/14 bug: only 8 chunks/row were loaded -> cols 32..127 stale.)
__device__ __forceinline__ void cp_tile64(float* sDst, const float* __restrict__ gSrc,
                                          int ptid) {
#pragma unroll
    for (int it = 0; it < 16; it++) {
        int idx = ptid + it * 128;          // 2048 16B-chunks
        int row = idx >> 5, q = idx & 31;
        unsigned sa = (unsigned)__cvta_generic_to_shared(sDst + row * SE_STRIDE + q * 4);
        asm volatile("cp.async.cg.shared.global [%0], [%1], 16;\n"
                     :: "r"(sa), "l"(gSrc + (size_t)row * 128 + q * 4));
    }
}

__device__ __forceinline__ void bar_sync(int id, int cnt) {
    asm volatile("bar.sync %0, %1;" :: "r"(id), "r"(cnt) : "memory");
}

// ---------------- kernel 0: zero output + z accumulators ----------------
__global__ void k_zero(float* __restrict__ out) {
    int i = blockIdx.x * blockDim.x + threadIdx.x;
    const int n_out4 = N_NODES * HD / 4;
    const int n_z4 = N_NODES * NHEADS / 4;
    float4 z = make_float4(0.f, 0.f, 0.f, 0.f);
    if (i < n_out4) ((float4*)out)[i] = z;
    else if (i < n_out4 + n_z4) ((float4*)g_Z)[i - n_out4] = z;
}

// ---------------- kernel 1: QKV projections (tf32, unchanged) -----------
__global__ void __launch_bounds__(512, 1)
k_proj(const float* __restrict__ h,
       const float* __restrict__ Wq, const float* __restrict__ bq,
       const float* __restrict__ Wk, const float* __restrict__ bk,
       const float* __restrict__ Wv, const float* __restrict__ bv) {
    float* smem = (float*)smem_raw;
    float* sA = smem;
    float* sB = sA + TILE * SA_STRIDE;
    float* sBias = sB + TILE * SA_STRIDE;

    const float* W; const float* b; float* outp;
    if (blockIdx.y == 0)      { W = Wq; b = bq; outp = g_Q; }
    else if (blockIdx.y == 1) { W = Wk; b = bk; outp = g_K; }
    else                      { W = Wv; b = bv; outp = g_V; }

    int tid = threadIdx.x;
    int lane = tid & 31, wid = tid >> 5;
    int warp_m = wid & 3, warp_n = wid >> 2;
    int node0 = blockIdx.x * TILE;
    int rows = N_NODES - node0; if (rows > TILE) rows = TILE;

    if (tid < 128) sBias[tid] = b[tid];
    load_tile_tf32<512>(sA, h + (size_t)node0 * 128, rows, tid);
    load_tile_tf32<512>(sB, W, 128, tid);
    __syncthreads();

    float acc[2][4][4];
#pragma unroll
    for (int mt = 0; mt < 2; mt++)
#pragma unroll
        for (int nt = 0; nt < 4; nt++)
#pragma unroll
            for (int i = 0; i < 4; i++) acc[mt][nt][i] = 0.f;

    int gid = lane >> 2, tig = lane & 3;
#pragma unroll
    for (int kk = 0; kk < 16; kk++) {
        int k0 = kk * 8;
        unsigned a[2][4];
#pragma unroll
        for (int mt = 0; mt < 2; mt++) {
            int r = warp_m * 32 + mt * 16 + gid;
            a[mt][0] = __float_as_uint(sA[r * SA_STRIDE + k0 + tig]);
            a[mt][1] = __float_as_uint(sA[(r + 8) * SA_STRIDE + k0 + tig]);
            a[mt][2] = __float_as_uint(sA[r * SA_STRIDE + k0 + tig + 4]);
            a[mt][3] = __float_as_uint(sA[(r + 8) * SA_STRIDE + k0 + tig + 4]);
        }
#pragma unroll
        for (int nt = 0; nt < 4; nt++) {
            int c = warp_n * 32 + nt * 8 + gid;
            unsigned b0 = __float_as_uint(sB[c * SA_STRIDE + k0 + tig]);
            unsigned b1 = __float_as_uint(sB[c * SA_STRIDE + k0 + tig + 4]);
            mma_tf32(acc[0][nt], a[0][0], a[0][1], a[0][2], a[0][3], b0, b1);
            mma_tf32(acc[1][nt], a[1][0], a[1][1], a[1][2], a[1][3], b0, b1);
        }
    }

#pragma unroll
    for (int nt = 0; nt < 4; nt++) {
        int c = warp_n * 32 + nt * 8 + 2 * tig;
        float b0 = sBias[c], b1 = sBias[c + 1];
#pragma unroll
        for (int mt = 0; mt < 2; mt++) {
            int r0 = warp_m * 32 + mt * 16 + gid;
            if (r0 < rows)
                *((float2*)(outp + (size_t)(node0 + r0) * 128 + c)) =
                    make_float2(acc[mt][nt][0] + b0, acc[mt][nt][1] + b1);
            int r1 = r0 + 8;
            if (r1 < rows)
                *((float2*)(outp + (size_t)(node0 + r1) * 128 + c)) =
                    make_float2(acc[mt][nt][2] + b0, acc[mt][nt][3] + b1);
        }
    }
}

// ---------------- kernel 2: warp-specialized edge kernel -----------------
// 512 threads = 2 halves x (4 producer warps + 4 consumer warps).
// Producers: cp.async e, fp16 mma GEMM, stage acc+be (fp16) into sAcc.
// Consumers: coalesced K/Q reads, score, exp, z-atomic, V-scatter.
// Handshake: bar.sync rendezvous only. GEMM(t+1) overlaps epilogue(t).
__global__ void __launch_bounds__(512, 1)
k_edge(const float* __restrict__ e, const int* __restrict__ src, const int* __restrict__ dst,
       const float* __restrict__ We, const float* __restrict__ be, float* __restrict__ out) {
    char* smem = smem_raw;
    __half* sWh = (__half*)(smem + SO_WH);
    float* sBe = (float*)(smem + SO_BE);

    int tid = threadIdx.x;
    int half = tid >> 8, htid = tid & 255;
    int lane = tid & 31;
    int hwid = htid >> 5;               // 0..7 within half

    // stage W fp16 k-interleaved: (b0,b1) for (2tig,2tig+1,2tig+8,2tig+9) = one LDS.64
    for (int idx = tid; idx < 128 * 128; idx += 512) {
        int c = idx >> 7, k = idx & 127;
        int pc = (k & ~15) | ((((k & 7) >> 1)) << 2) | (k & 1) | (((k >> 3) & 1) << 1);
        sWh[c * SWH_STRIDE + pc] = __float2half_rn(We[idx]);
    }
    if (tid < 128) sBe[tid] = be[tid];
    __syncthreads();

    float* hEb = (float*)(smem + SO_HALF0 + half * HALF_BYTES);          // 2x[64][136] f32
    __half* sAcc = (__half*)((char*)hEb + HALF_EBUF);                    // [64][136] f16

    const int PROD = 1 + half * 3, DONE = 2 + half * 3, READY = 3 + half * 3;
    const int stride = gridDim.x * 2;
    const int p0 = blockIdx.x * 2 + half;

    if (hwid < 4) {
        // ================= PRODUCER =================
        int ptid = htid;                 // 0..127
        int pw = hwid;                   // 0..3
        int warp_m = pw & 1, warp_n = pw >> 1;
        int gid = lane >> 2, tig = lane & 3;

        if (p0 < NTILES64) cp_tile64(hEb, e + (size_t)p0 * TILE_M * 128, ptid);
        asm volatile("cp.async.commit_group;" ::: "memory");
        if (p0 + stride < NTILES64)
            cp_tile64(hEb + TILE_M * SE_STRIDE, e + (size_t)(p0 + stride) * TILE_M * 128, ptid);
        asm volatile("cp.async.commit_group;" ::: "memory");

        int k = 0;
        for (int t = p0; t < NTILES64; t += stride, k++) {
            asm volatile("cp.async.wait_group 1;" ::: "memory");
            bar_sync(PROD, 128);         // e(t) visible to all producer warps

            float* sE = hEb + (k & 1) * TILE_M * SE_STRIDE;

            float acc[2][8][4];
#pragma unroll
            for (int mt = 0; mt < 2; mt++)
#pragma unroll
                for (int nt = 0; nt < 8; nt++)
#pragma unroll
                    for (int i = 0; i < 4; i++) acc[mt][nt][i] = 0.f;

#pragma unroll
            for (int ks = 0; ks < 8; ks++) {
                int k0 = ks * 16;
                unsigned a[2][4];
#pragma unroll
                for (int mt = 0; mt < 2; mt++) {
                    int r = warp_m * 32 + mt * 16 + gid;
                    float2 f0 = *(const float2*)(sE + r * SE_STRIDE + k0 + 2 * tig);
                    float2 f1 = *(const float2*)(sE + (r + 8) * SE_STRIDE + k0 + 2 * tig);
                    float2 f2 = *(const float2*)(sE + r * SE_STRIDE + k0 + 8 + 2 * tig);
                    float2 f3 = *(const float2*)(sE + (r + 8) * SE_STRIDE + k0 + 8 + 2 * tig);
                    a[mt][0] = cvt_h2(f0); a[mt][1] = cvt_h2(f1);
                    a[mt][2] = cvt_h2(f2); a[mt][3] = cvt_h2(f3);
                }
#pragma unroll
                for (int nt = 0; nt < 8; nt++) {
                    int c = warp_n * 64 + nt * 8 + gid;
                    uint2 bv = *(const uint2*)(sWh + c * SWH_STRIDE + k0 + 4 * tig);
                    mma_f16(acc[0][nt], a[0], bv.x, bv.y);
                    mma_f16(acc[1][nt], a[1], bv.x, bv.y);
                }
            }
            bar_sync(PROD, 128);         // all producer reads of sE done

            int t2 = t + 2 * stride;
            if (t2 < NTILES64) cp_tile64(sE, e + (size_t)t2 * TILE_M * 128, ptid);
            asm volatile("cp.async.commit_group;" ::: "memory");

            if (k > 0) bar_sync(DONE, 256);   // consumers done with sAcc(t-1)

            // stage acc + be into sAcc (fp16)
#pragma unroll
            for (int nt = 0; nt < 8; nt++) {
                int c = warp_n * 64 + nt * 8 + 2 * tig;
                float b0 = sBe[c], b1 = sBe[c + 1];
#pragma unroll
                for (int mt = 0; mt < 2; mt++) {
                    int r0 = warp_m * 32 + mt * 16 + gid;
                    *(unsigned*)(sAcc + r0 * SACC_STRIDE + c) =
                        cvt_h2(make_float2(acc[mt][nt][0] + b0, acc[mt][nt][1] + b1));
                    *(unsigned*)(sAcc + (r0 + 8) * SACC_STRIDE + c) =
                        cvt_h2(make_float2(acc[mt][nt][2] + b0, acc[mt][nt][3] + b1));
                }
            }
            bar_sync(READY, 256);        // rendezvous: sAcc(t) published (STS drained)
        }
    } else {
        // ================= CONSUMER =================
        int ew = hwid - 4;               // 0..3

        for (int t = p0; t < NTILES64; t += stride) {
            bar_sync(READY, 256);        // sAcc(t) ready

#pragma unroll 4
            for (int i = 0; i < 16; i++) {
                int row = ew * 16 + i;
                int ge = t * TILE_M + row;
                int sN = __ldg(&src[ge]);
                int dN = __ldg(&dst[ge]);
                const float4* Kp = (const float4*)(g_K + (size_t)sN * 128);
                const float4* Qp = (const float4*)(g_Q + (size_t)dN * 128);
                float4 kv = Kp[lane], qv = Qp[lane];
                uint2 epk = *(const uint2*)(sAcc + row * SACC_STRIDE + lane * 4);
                float2 e01 = __half22float2(*(__half2*)&epk.x);
                float2 e23 = __half22float2(*(__half2*)&epk.y);
                float p = kv.x * qv.x * e01.x + kv.y * qv.y * e01.y
                        + kv.z * qv.z * e23.x + kv.w * qv.w * e23.y;
                p += __shfl_xor_sync(0xffffffffu, p, 1);
                p += __shfl_xor_sync(0xffffffffu, p, 2);
                float s = 0.f;
                if ((lane & 3) == 0) {
                    s = __expf(fminf(fmaxf(p * 0.25f, -5.f), 5.f));
                    atomicAdd(&g_Z[(size_t)dN * NHEADS + (lane >> 2)], s);
                }
                s = __shfl_sync(0xffffffffu, s, lane & ~3);
                float4 vv = ((const float4*)(g_V + (size_t)sN * 128))[lane];
                float4 r = make_float4(vv.x * s, vv.y * s, vv.z * s, vv.w * s);
                atomicAdd((float4*)(out + (size_t)dN * 128 + lane * 4), r);
            }
            if (t + stride < NTILES64) bar_sync(DONE, 256);  // release sAcc
        }
    }
}

// ---------------- kernel 3: normalize -----------------------------------
__global__ void k_final(float* __restrict__ out) {
    int i = blockIdx.x * blockDim.x + threadIdx.x;  // float4 index
    if (i >= N_NODES * HD / 4) return;
    int node = i >> 5;
    int head = (i & 31) >> 2;
    float z = 1.0f / (g_Z[node * NHEADS + head] + 1e-6f);
    float4 v = ((float4*)out)[i];
    v.x *= z; v.y *= z; v.z *= z; v.w *= z;
    ((float4*)out)[i] = v;
}

// ---------------- launcher ------------------------------------------------
extern "C" void kernel_launch(void* const* d_in, const int* in_sizes, int n_in,
                              void* d_out, int out_size) {
    (void)in_sizes; (void)n_in; (void)out_size;
    const float* h  = (const float*)d_in[0];
    const float* e  = (const float*)d_in[1];
    const int*   src = (const int*)d_in[2];
    const int*   dst = (const int*)d_in[3];
    const float* Wq = (const float*)d_in[4];
    const float* bq = (const float*)d_in[5];
    const float* Wk = (const float*)d_in[6];
    const float* bk = (const float*)d_in[7];
    const float* We = (const float*)d_in[8];
    const float* be = (const float*)d_in[9];
    const float* Wv = (const float*)d_in[10];
    const float* bv = (const float*)d_in[11];
    float* out = (float*)d_out;

    cudaFuncSetAttribute(k_proj, cudaFuncAttributeMaxDynamicSharedMemorySize, SMEM_PROJ);
    cudaFuncSetAttribute(k_edge, cudaFuncAttributeMaxDynamicSharedMemorySize, SMEM_EDGE);

    k_zero<<<(N_NODES * HD / 4 + N_NODES * NHEADS / 4 + 255) / 256, 256>>>(out);
    k_proj<<<dim3((N_NODES + TILE - 1) / TILE, 3), 512, SMEM_PROJ>>>(h, Wq, bq, Wk, bk, Wv, bv);
    k_edge<<<EDGE_GRID, 512, SMEM_EDGE>>>(e, src, dst, We, be, out);
    k_final<<<(N_NODES * HD / 4 + 255) / 256, 256>>>(out);
}